// round 12
// baseline (speedup 1.0000x reference)
#include <cuda_runtime.h>
#include <math.h>

// ---------------------------------------------------------------------------
// SimpleNet quanvolutional pipeline, sm_103a
//   g_h1: [4][255][256]  (row stride 256)
//   g_h2: [20][125][128] (row stride 128)
// R10 best-measured kernels; k_fc folded into k_conv3 via last-block pattern.
// ---------------------------------------------------------------------------

typedef unsigned long long u64;

__device__ __forceinline__ u64 f2pack(float lo, float hi) {
    u64 r; asm("mov.b64 %0, {%1, %2};" : "=l"(r) : "f"(lo), "f"(hi)); return r;
}
__device__ __forceinline__ void f2unpack(u64 v, float& lo, float& hi) {
    asm("mov.b64 {%0, %1}, %2;" : "=f"(lo), "=f"(hi) : "l"(v));
}
__device__ __forceinline__ u64 f2fma(u64 a, u64 b, u64 c) {
    u64 d; asm("fma.rn.f32x2 %0, %1, %2, %3;" : "=l"(d) : "l"(a), "l"(b), "l"(c)); return d;
}

__device__ float g_U[512];                 // [2][16][16]: Wr rows then Wi rows
__device__ float g_h1[4 * 255 * 256];
__device__ float g_h2[20 * 125 * 128];
__device__ float g_bins[640];              // adaptive-max bins (atomicMax as int)
__device__ int   g_done;                   // conv3 completion counter (self-resetting)

#define H1_STRIDE 256
#define H1_PLANE  (255 * 256)
#define H2_STRIDE 128
#define H2_PLANE  (125 * 128)
#define CONV3_BLOCKS 640

// ---------------------------------------------------------------------------
// k_prep: simulate weight circuit -> U, export W[k][j] = U[k][j]*(-i)^popc(j).
// Zero adaptive-max bins.
// ---------------------------------------------------------------------------
__global__ void k_prep(const float* __restrict__ qw) {
    int t = threadIdx.x;                 // 0..255
    for (int b = t; b < 640; b += 256) ((int*)g_bins)[b] = 0;

    __shared__ float Ur[16][16], Ui[16][16];

    if (t < 16) {
        int k = t;
        float pr[16], pi[16];
        #pragma unroll
        for (int i = 0; i < 16; i++) { pr[i] = (i == k) ? 1.f : 0.f; pi[i] = 0.f; }

        for (int l = 0; l < 3; l++) {
            for (int w = 0; w < 4; w++) {
                float phi = qw[(l * 4 + w) * 3 + 0];
                float th  = qw[(l * 4 + w) * 3 + 1];
                float om  = qw[(l * 4 + w) * 3 + 2];
                float st, ct, sap, cap, sam, cam;
                sincosf(0.5f * th, &st, &ct);
                sincosf(0.5f * (phi + om), &sap, &cap);
                sincosf(0.5f * (phi - om), &sam, &cam);
                float u00r =  cap * ct, u00i = -sap * ct;
                float u01r = -cam * st, u01i = -sam * st;
                float u10r =  cam * st, u10i = -sam * st;
                float u11r =  cap * ct, u11i =  sap * ct;
                int m = 8 >> w;
                for (int i0 = 0; i0 < 16; i0++) {
                    if (i0 & m) continue;
                    int i1 = i0 | m;
                    float a0r = pr[i0], a0i = pi[i0];
                    float a1r = pr[i1], a1i = pi[i1];
                    pr[i0] = u00r * a0r - u00i * a0i + u01r * a1r - u01i * a1i;
                    pi[i0] = u00r * a0i + u00i * a0r + u01r * a1i + u01i * a1r;
                    pr[i1] = u10r * a0r - u10i * a0i + u11r * a1r - u11i * a1i;
                    pi[i1] = u10r * a0i + u10i * a0r + u11r * a1i + u11i * a1r;
                }
            }
            int r = l % 3 + 1;
            for (int w = 0; w < 4; w++) {
                int cm = 8 >> w;
                int tm = 8 >> ((w + r) & 3);
                for (int i = 0; i < 16; i++) {
                    if ((i & cm) && !(i & tm)) {
                        int j = i | tm;
                        float tr = pr[i], ti = pi[i];
                        pr[i] = pr[j]; pi[i] = pi[j];
                        pr[j] = tr;    pi[j] = ti;
                    }
                }
            }
        }
        #pragma unroll
        for (int i = 0; i < 16; i++) { Ur[i][k] = pr[i]; Ui[i][k] = pi[i]; }
    }
    __syncthreads();

    int i = t >> 4, j = t & 15;
    float ur = Ur[i][j], ui = Ui[i][j];
    int d = __popc(j) & 3;
    float wr = (d == 0) ? ur : (d == 1) ? ui : (d == 2) ? -ur : -ui;
    float wi = (d == 0) ? ui : (d == 1) ? -ur : (d == 2) ? -ui : ur;
    g_U[t]       = wr;
    g_U[256 + t] = wi;
}

// ---------------------------------------------------------------------------
// k_qconv: scalar form (best measured). psi = W r per patch; ez; max-pool;
// sigmoid -> g_h1.
// ---------------------------------------------------------------------------
__global__ void __launch_bounds__(128) k_qconv(const float* __restrict__ img) {
    __shared__ __align__(16) float4 Us[128];   // Wr rows (64 f4) then Wi rows
    {
        int tid = threadIdx.y * 16 + threadIdx.x;
        if (tid < 128) Us[tid] = ((const float4*)g_U)[tid];
    }
    __syncthreads();

    int px = blockIdx.x * 16 + threadIdx.x;
    int py = blockIdx.y * 8 + threadIdx.y;
    if (px >= 255 || py >= 255) return;

    float cc[9], ss[9];
    int y0 = 2 * py, x0 = 2 * px;
    #pragma unroll
    for (int d = 0; d < 9; d++) {
        int dy = d / 3, dx = d % 3;
        float v = 0.5f * img[(y0 + dy) * 512 + (x0 + dx)];
        __sincosf(v, &ss[d], &cc[d]);
    }

    float r[4][16];
    #pragma unroll
    for (int p = 0; p < 4; p++) {
        int dy = p >> 1, dx = p & 1;
        int ia = dy * 3 + dx, ib = ia + 1, ic = ia + 3, id = ia + 4;
        float c0 = cc[ia], s0 = ss[ia], c1 = cc[ib], s1 = ss[ib];
        float c2 = cc[ic], s2 = ss[ic], c3 = cc[id], s3 = ss[id];
        float hi[4] = { c0 * c1, c0 * s1, s0 * c1, s0 * s1 };
        float lo[4] = { c2 * c3, c2 * s3, s2 * c3, s2 * s3 };
        #pragma unroll
        for (int a = 0; a < 4; a++)
            #pragma unroll
            for (int b = 0; b < 4; b++)
                r[p][a * 4 + b] = hi[a] * lo[b];
    }

    float ez[4][4];
    #pragma unroll
    for (int p = 0; p < 4; p++)
        #pragma unroll
        for (int w = 0; w < 4; w++) ez[p][w] = 0.f;

    #pragma unroll
    for (int k = 0; k < 16; k++) {
        float4 u0 = Us[k * 4 + 0], u1 = Us[k * 4 + 1];
        float4 u2 = Us[k * 4 + 2], u3 = Us[k * 4 + 3];
        float4 v0 = Us[64 + k * 4 + 0], v1 = Us[64 + k * 4 + 1];
        float4 v2 = Us[64 + k * 4 + 2], v3 = Us[64 + k * 4 + 3];
        #pragma unroll
        for (int p = 0; p < 4; p++) {
            float sr = u0.x * r[p][0]  + u0.y * r[p][1]  + u0.z * r[p][2]  + u0.w * r[p][3]
                     + u1.x * r[p][4]  + u1.y * r[p][5]  + u1.z * r[p][6]  + u1.w * r[p][7]
                     + u2.x * r[p][8]  + u2.y * r[p][9]  + u2.z * r[p][10] + u2.w * r[p][11]
                     + u3.x * r[p][12] + u3.y * r[p][13] + u3.z * r[p][14] + u3.w * r[p][15];
            float si = v0.x * r[p][0]  + v0.y * r[p][1]  + v0.z * r[p][2]  + v0.w * r[p][3]
                     + v1.x * r[p][4]  + v1.y * r[p][5]  + v1.z * r[p][6]  + v1.w * r[p][7]
                     + v2.x * r[p][8]  + v2.y * r[p][9]  + v2.z * r[p][10] + v2.w * r[p][11]
                     + v3.x * r[p][12] + v3.y * r[p][13] + v3.z * r[p][14] + v3.w * r[p][15];
            float pk = sr * sr + si * si;
            ez[p][0] += (k & 8) ? -pk : pk;
            ez[p][1] += (k & 4) ? -pk : pk;
            ez[p][2] += (k & 2) ? -pk : pk;
            ez[p][3] += (k & 1) ? -pk : pk;
        }
    }

    #pragma unroll
    for (int w = 0; w < 4; w++) {
        float m = fmaxf(fmaxf(ez[0][w], ez[1][w]), fmaxf(ez[2][w], ez[3][w]));
        g_h1[w * H1_PLANE + py * H1_STRIDE + px] = 1.f / (1.f + __expf(-m));
    }
}

// ---------------------------------------------------------------------------
// k_conv2: 5x5 conv (4->20) + relu + pool2 -> g_h2.
// Scalar 2co x 2pp (best measured). Block (16,8) covers 32x8 pooled px.
// Grid (4,16,10) = 640 blocks.
// ---------------------------------------------------------------------------
__global__ void __launch_bounds__(128) k_conv2(const float* __restrict__ w2,
                                               const float* __restrict__ b2) {
    int cog = blockIdx.z;                      // co = cog*2, cog*2+1
    __shared__ float ws[2][100];
    __shared__ __align__(16) float tile[4][20][68];
    int tx = threadIdx.x, ty = threadIdx.y;
    int tid = ty * 16 + tx;

    for (int q = tid; q < 200; q += 128) {
        int co = q / 100, rr = q % 100;
        ws[co][rr] = w2[(cog * 2 + co) * 100 + rr];
    }

    int ix0 = blockIdx.x * 64, iy0 = blockIdx.y * 16;   // pre-pool origin
    for (int q = tid; q < 4 * 20 * 17; q += 128) {
        int ci = q / 340, rem = q % 340, ry = rem / 17, f4 = rem % 17;
        int gy = iy0 + ry, gx = ix0 + f4 * 4;
        float4 v = make_float4(0.f, 0.f, 0.f, 0.f);
        if (gy < 255) {
            const float* src = &g_h1[ci * H1_PLANE + gy * H1_STRIDE + gx];
            if (gx + 3 < 255) {
                v = *(const float4*)src;
            } else {
                if (gx + 0 < 255) v.x = src[0];
                if (gx + 1 < 255) v.y = src[1];
                if (gx + 2 < 255) v.z = src[2];
                if (gx + 3 < 255) v.w = src[3];
            }
        }
        *(float4*)&tile[ci][ry][f4 * 4] = v;
    }
    __syncthreads();

    float acc[2][2][4];
    #pragma unroll
    for (int co = 0; co < 2; co++)
        #pragma unroll
        for (int pp = 0; pp < 2; pp++)
            #pragma unroll
            for (int q = 0; q < 4; q++) acc[co][pp][q] = 0.f;

    int ly = 2 * ty, lx = 4 * tx;              // local pre-pool origin
    #pragma unroll
    for (int ci = 0; ci < 4; ci++) {
        float patch[6][8];
        #pragma unroll
        for (int rr = 0; rr < 6; rr++) {
            const float4* rp = (const float4*)&tile[ci][ly + rr][lx];
            float4 v0 = rp[0], v1 = rp[1];
            patch[rr][0] = v0.x; patch[rr][1] = v0.y;
            patch[rr][2] = v0.z; patch[rr][3] = v0.w;
            patch[rr][4] = v1.x; patch[rr][5] = v1.y;
            patch[rr][6] = v1.z; patch[rr][7] = v1.w;
        }
        #pragma unroll
        for (int co = 0; co < 2; co++) {
            #pragma unroll
            for (int ky = 0; ky < 5; ky++) {
                #pragma unroll
                for (int kx = 0; kx < 5; kx++) {
                    float wv = ws[co][ci * 25 + ky * 5 + kx];
                    #pragma unroll
                    for (int pp = 0; pp < 2; pp++) {
                        int c = 2 * pp + kx;
                        acc[co][pp][0] += wv * patch[ky][c];
                        acc[co][pp][1] += wv * patch[ky][c + 1];
                        acc[co][pp][2] += wv * patch[ky + 1][c];
                        acc[co][pp][3] += wv * patch[ky + 1][c + 1];
                    }
                }
            }
        }
    }

    int py = blockIdx.y * 8 + ty;
    #pragma unroll
    for (int co = 0; co < 2; co++) {
        float bb = b2[cog * 2 + co];
        #pragma unroll
        for (int pp = 0; pp < 2; pp++) {
            int px = blockIdx.x * 32 + 2 * tx + pp;
            if (px >= 125 || py >= 125) continue;
            float m = fmaxf(fmaxf(acc[co][pp][0], acc[co][pp][1]),
                            fmaxf(acc[co][pp][2], acc[co][pp][3]));
            m = fmaxf(m + bb, 0.f);
            g_h2[(cog * 2 + co) * H2_PLANE + py * H2_STRIDE + px] = m;
        }
    }
}

// ---------------------------------------------------------------------------
// k_conv3: 3x3 conv (20->40) + relu + adaptive-max + (last block) FC stack.
// Block (16,16): two ty-halves = two co-pairs sharing one double-buffered
// tile. Thread: 2 horiz px; f32x2 lanes = co pair. Grid (4,16,10) = 640.
// Bins over 123: bin b = [floor(b*123/4), ceil((b+1)*123/4)); overlap rows
// 30,61,92 also belong to the NEXT bin.
// ---------------------------------------------------------------------------
__global__ void __launch_bounds__(256) k_conv3(const float* __restrict__ w3,
                                               const float* __restrict__ b3,
                                               const float* __restrict__ fw1,
                                               const float* __restrict__ fb1,
                                               const float* __restrict__ fw2,
                                               const float* __restrict__ fb2,
                                               float* __restrict__ out) {
    int cog2 = blockIdx.z;                     // co base = cog2*4
    __shared__ u64 ws2[2][180];                // [half] (w_co0, w_co1)
    __shared__ __align__(16) float tile[2][5][10][36];
    __shared__ int sbins[4][16];
    int tx = threadIdx.x, ty = threadIdx.y;
    int tid = ty * 16 + tx;
    int half = ty >> 3;                        // 0/1 -> co pair
    int tyl  = ty & 7;                         // row within 8-row band

    for (int q = tid; q < 360; q += 256) {
        int h = q / 180, rr = q % 180;
        ws2[h][rr] = f2pack(w3[(cog2 * 4 + h * 2 + 0) * 180 + rr],
                            w3[(cog2 * 4 + h * 2 + 1) * 180 + rr]);
    }
    if (tid < 64) ((int*)sbins)[tid] = 0;

    int px0 = blockIdx.x * 32, py0 = blockIdx.y * 8;
    int lx = 2 * tx;

    auto fill = [&](int c, int b) {
        for (int q = tid; q < 450; q += 256) {
            int cil = q / 90, rem = q % 90, ry = rem / 9, f4 = rem % 9;
            int gy = py0 + ry, gx = px0 + f4 * 4;
            float4 v = make_float4(0.f, 0.f, 0.f, 0.f);
            if (gy < 125 && gx < 125) {
                const float* src = &g_h2[(c * 5 + cil) * H2_PLANE + gy * H2_STRIDE + gx];
                if (gx + 3 < 125) {
                    v = *(const float4*)src;
                } else {
                    v.x = src[0];
                    if (gx + 1 < 125) v.y = src[1];
                    if (gx + 2 < 125) v.z = src[2];
                }
            }
            *(float4*)&tile[b][cil][ry][f4 * 4] = v;
        }
    };

    fill(0, 0);
    __syncthreads();

    u64 acc2[2] = {0ull, 0ull};                // 2 px, lanes = co pair

    for (int c4 = 0; c4 < 4; c4++) {
        int buf = c4 & 1;
        if (c4 < 3) fill(c4 + 1, buf ^ 1);     // overlap next chunk's loads

        #pragma unroll
        for (int cil = 0; cil < 5; cil++) {
            int ci = c4 * 5 + cil;
            float f[3][4];
            #pragma unroll
            for (int rr = 0; rr < 3; rr++) {
                const float2* rp = (const float2*)&tile[buf][cil][tyl + rr][lx];
                float2 v0 = rp[0], v1 = rp[1];
                f[rr][0] = v0.x; f[rr][1] = v0.y;
                f[rr][2] = v1.x; f[rr][3] = v1.y;
            }
            u64 p2[3][4];
            #pragma unroll
            for (int rr = 0; rr < 3; rr++)
                #pragma unroll
                for (int c = 0; c < 4; c++) p2[rr][c] = f2pack(f[rr][c], f[rr][c]);

            #pragma unroll
            for (int ky = 0; ky < 3; ky++) {
                #pragma unroll
                for (int kx = 0; kx < 3; kx++) {
                    u64 wv = ws2[half][ci * 9 + ky * 3 + kx];
                    acc2[0] = f2fma(wv, p2[ky][kx], acc2[0]);
                    acc2[1] = f2fma(wv, p2[ky][kx + 1], acc2[1]);
                }
            }
        }
        __syncthreads();
    }

    int gy = py0 + tyl;
    if (gy < 123) {
        int bi = (gy * 4) / 123; if (bi > 3) bi = 3;
        bool oy = (bi < 3) && (gy >= (((bi + 1) * 123) >> 2));
        float bb0 = b3[cog2 * 4 + half * 2 + 0];
        float bb1 = b3[cog2 * 4 + half * 2 + 1];
        int r0 = half * 2, r1 = half * 2 + 1;
        #pragma unroll
        for (int dx = 0; dx < 2; dx++) {
            int gx = px0 + lx + dx;
            if (gx >= 123) continue;
            float a0, a1;
            f2unpack(acc2[dx], a0, a1);
            float v0 = fmaxf(a0 + bb0, 0.f);
            float v1 = fmaxf(a1 + bb1, 0.f);
            int iv0 = __float_as_int(v0), iv1 = __float_as_int(v1);
            int bj = (gx * 4) / 123; if (bj > 3) bj = 3;
            bool ox = (bj < 3) && (gx >= (((bj + 1) * 123) >> 2));
            atomicMax(&sbins[r0][bi * 4 + bj], iv0);
            atomicMax(&sbins[r1][bi * 4 + bj], iv1);
            if (oy) { atomicMax(&sbins[r0][(bi + 1) * 4 + bj], iv0);
                      atomicMax(&sbins[r1][(bi + 1) * 4 + bj], iv1); }
            if (ox) { atomicMax(&sbins[r0][bi * 4 + (bj + 1)], iv0);
                      atomicMax(&sbins[r1][bi * 4 + (bj + 1)], iv1); }
            if (oy && ox) { atomicMax(&sbins[r0][(bi + 1) * 4 + (bj + 1)], iv0);
                            atomicMax(&sbins[r1][(bi + 1) * 4 + (bj + 1)], iv1); }
        }
    }
    __syncthreads();
    if (tid < 64) {
        int co = tid >> 4, b = tid & 15;
        atomicMax((int*)&g_bins[(cog2 * 4 + co) * 16 + b], sbins[co][b]);
    }

    // ---- last-block FC: 640 -> 64 (relu) -> 10 ----
    __shared__ int s_last;
    __threadfence();                            // make bin atomics visible
    __syncthreads();                            // all threads' atomics issued
    if (tid == 0) {
        int prev = atomicAdd(&g_done, 1);
        s_last = (prev == CONV3_BLOCKS - 1) ? 1 : 0;
    }
    __syncthreads();
    if (!s_last) return;

    __threadfence();                            // acquire all blocks' bins
    if (tid == 0) g_done = 0;                   // reset for next graph replay

    __shared__ float h[640];
    __shared__ float f1[64];
    for (int i = tid; i < 640; i += 256) h[i] = g_bins[i];
    __syncthreads();

    int warp = tid >> 5, lane = tid & 31;
    #pragma unroll
    for (int k = 0; k < 8; k++) {
        int n = warp * 8 + k;
        float s = 0.f;
        for (int j = lane; j < 640; j += 32) s += fw1[n * 640 + j] * h[j];
        s += __shfl_xor_sync(0xffffffffu, s, 16);
        s += __shfl_xor_sync(0xffffffffu, s, 8);
        s += __shfl_xor_sync(0xffffffffu, s, 4);
        s += __shfl_xor_sync(0xffffffffu, s, 2);
        s += __shfl_xor_sync(0xffffffffu, s, 1);
        if (lane == 0) f1[n] = fmaxf(s + fb1[n], 0.f);
    }
    __syncthreads();
    if (tid < 10) {
        float a = fb2[tid];
        #pragma unroll
        for (int j = 0; j < 64; j++) a += fw2[tid * 64 + j] * f1[j];
        out[tid] = a;
    }
}

// ---------------------------------------------------------------------------
extern "C" void kernel_launch(void* const* d_in, const int* in_sizes, int n_in,
                              void* d_out, int out_size) {
    const float* x   = (const float*)d_in[0];
    const float* qw  = (const float*)d_in[1];
    const float* c2w = (const float*)d_in[2];
    const float* c2b = (const float*)d_in[3];
    const float* c3w = (const float*)d_in[4];
    const float* c3b = (const float*)d_in[5];
    const float* f1w = (const float*)d_in[6];
    const float* f1b = (const float*)d_in[7];
    const float* f2w = (const float*)d_in[8];
    const float* f2b = (const float*)d_in[9];

    k_prep<<<1, 256>>>(qw);

    dim3 bq(16, 8), gq(16, 32);
    k_qconv<<<gq, bq>>>(x);

    dim3 bc(16, 8);
    dim3 g2(4, 16, 10);
    k_conv2<<<g2, bc>>>(c2w, c2b);

    dim3 bc3(16, 16);
    dim3 g3(4, 16, 10);
    k_conv3<<<g3, bc3>>>(c3w, c3b, f1w, f1b, f2w, f2b, (float*)d_out);
}

// round 13
// speedup vs baseline: 1.0505x; 1.0505x over previous
#include <cuda_runtime.h>
#include <math.h>

// ---------------------------------------------------------------------------
// SimpleNet quanvolutional pipeline, sm_103a
//   g_h1: [4][255][256]  (row stride 256)
//   g_h2: [20][125][128] (row stride 128)
// R10 best-measured kernels; k_fc folded into k_conv3 via last-block pattern
// with writer-only fences (threadFenceReduction pattern).
// ---------------------------------------------------------------------------

typedef unsigned long long u64;

__device__ __forceinline__ u64 f2pack(float lo, float hi) {
    u64 r; asm("mov.b64 %0, {%1, %2};" : "=l"(r) : "f"(lo), "f"(hi)); return r;
}
__device__ __forceinline__ void f2unpack(u64 v, float& lo, float& hi) {
    asm("mov.b64 {%0, %1}, %2;" : "=f"(lo), "=f"(hi) : "l"(v));
}
__device__ __forceinline__ u64 f2fma(u64 a, u64 b, u64 c) {
    u64 d; asm("fma.rn.f32x2 %0, %1, %2, %3;" : "=l"(d) : "l"(a), "l"(b), "l"(c)); return d;
}

__device__ float g_U[512];                 // [2][16][16]: Wr rows then Wi rows
__device__ float g_h1[4 * 255 * 256];
__device__ float g_h2[20 * 125 * 128];
__device__ float g_bins[640];              // adaptive-max bins (atomicMax as int)
__device__ int   g_done;                   // conv3 completion counter (self-resetting)

#define H1_STRIDE 256
#define H1_PLANE  (255 * 256)
#define H2_STRIDE 128
#define H2_PLANE  (125 * 128)
#define CONV3_BLOCKS 640

// ---------------------------------------------------------------------------
// k_prep: simulate weight circuit -> U, export W[k][j] = U[k][j]*(-i)^popc(j).
// Zero adaptive-max bins.
// ---------------------------------------------------------------------------
__global__ void k_prep(const float* __restrict__ qw) {
    int t = threadIdx.x;                 // 0..255
    for (int b = t; b < 640; b += 256) ((int*)g_bins)[b] = 0;

    __shared__ float Ur[16][16], Ui[16][16];

    if (t < 16) {
        int k = t;
        float pr[16], pi[16];
        #pragma unroll
        for (int i = 0; i < 16; i++) { pr[i] = (i == k) ? 1.f : 0.f; pi[i] = 0.f; }

        for (int l = 0; l < 3; l++) {
            for (int w = 0; w < 4; w++) {
                float phi = qw[(l * 4 + w) * 3 + 0];
                float th  = qw[(l * 4 + w) * 3 + 1];
                float om  = qw[(l * 4 + w) * 3 + 2];
                float st, ct, sap, cap, sam, cam;
                sincosf(0.5f * th, &st, &ct);
                sincosf(0.5f * (phi + om), &sap, &cap);
                sincosf(0.5f * (phi - om), &sam, &cam);
                float u00r =  cap * ct, u00i = -sap * ct;
                float u01r = -cam * st, u01i = -sam * st;
                float u10r =  cam * st, u10i = -sam * st;
                float u11r =  cap * ct, u11i =  sap * ct;
                int m = 8 >> w;
                for (int i0 = 0; i0 < 16; i0++) {
                    if (i0 & m) continue;
                    int i1 = i0 | m;
                    float a0r = pr[i0], a0i = pi[i0];
                    float a1r = pr[i1], a1i = pi[i1];
                    pr[i0] = u00r * a0r - u00i * a0i + u01r * a1r - u01i * a1i;
                    pi[i0] = u00r * a0i + u00i * a0r + u01r * a1i + u01i * a1r;
                    pr[i1] = u10r * a0r - u10i * a0i + u11r * a1r - u11i * a1i;
                    pi[i1] = u10r * a0i + u10i * a0r + u11r * a1i + u11i * a1r;
                }
            }
            int r = l % 3 + 1;
            for (int w = 0; w < 4; w++) {
                int cm = 8 >> w;
                int tm = 8 >> ((w + r) & 3);
                for (int i = 0; i < 16; i++) {
                    if ((i & cm) && !(i & tm)) {
                        int j = i | tm;
                        float tr = pr[i], ti = pi[i];
                        pr[i] = pr[j]; pi[i] = pi[j];
                        pr[j] = tr;    pi[j] = ti;
                    }
                }
            }
        }
        #pragma unroll
        for (int i = 0; i < 16; i++) { Ur[i][k] = pr[i]; Ui[i][k] = pi[i]; }
    }
    __syncthreads();

    int i = t >> 4, j = t & 15;
    float ur = Ur[i][j], ui = Ui[i][j];
    int d = __popc(j) & 3;
    float wr = (d == 0) ? ur : (d == 1) ? ui : (d == 2) ? -ur : -ui;
    float wi = (d == 0) ? ui : (d == 1) ? -ur : (d == 2) ? -ui : ur;
    g_U[t]       = wr;
    g_U[256 + t] = wi;
}

// ---------------------------------------------------------------------------
// k_qconv: scalar form (best measured). psi = W r per patch; ez; max-pool;
// sigmoid -> g_h1.
// ---------------------------------------------------------------------------
__global__ void __launch_bounds__(128) k_qconv(const float* __restrict__ img) {
    __shared__ __align__(16) float4 Us[128];   // Wr rows (64 f4) then Wi rows
    {
        int tid = threadIdx.y * 16 + threadIdx.x;
        if (tid < 128) Us[tid] = ((const float4*)g_U)[tid];
    }
    __syncthreads();

    int px = blockIdx.x * 16 + threadIdx.x;
    int py = blockIdx.y * 8 + threadIdx.y;
    if (px >= 255 || py >= 255) return;

    float cc[9], ss[9];
    int y0 = 2 * py, x0 = 2 * px;
    #pragma unroll
    for (int d = 0; d < 9; d++) {
        int dy = d / 3, dx = d % 3;
        float v = 0.5f * img[(y0 + dy) * 512 + (x0 + dx)];
        __sincosf(v, &ss[d], &cc[d]);
    }

    float r[4][16];
    #pragma unroll
    for (int p = 0; p < 4; p++) {
        int dy = p >> 1, dx = p & 1;
        int ia = dy * 3 + dx, ib = ia + 1, ic = ia + 3, id = ia + 4;
        float c0 = cc[ia], s0 = ss[ia], c1 = cc[ib], s1 = ss[ib];
        float c2 = cc[ic], s2 = ss[ic], c3 = cc[id], s3 = ss[id];
        float hi[4] = { c0 * c1, c0 * s1, s0 * c1, s0 * s1 };
        float lo[4] = { c2 * c3, c2 * s3, s2 * c3, s2 * s3 };
        #pragma unroll
        for (int a = 0; a < 4; a++)
            #pragma unroll
            for (int b = 0; b < 4; b++)
                r[p][a * 4 + b] = hi[a] * lo[b];
    }

    float ez[4][4];
    #pragma unroll
    for (int p = 0; p < 4; p++)
        #pragma unroll
        for (int w = 0; w < 4; w++) ez[p][w] = 0.f;

    #pragma unroll
    for (int k = 0; k < 16; k++) {
        float4 u0 = Us[k * 4 + 0], u1 = Us[k * 4 + 1];
        float4 u2 = Us[k * 4 + 2], u3 = Us[k * 4 + 3];
        float4 v0 = Us[64 + k * 4 + 0], v1 = Us[64 + k * 4 + 1];
        float4 v2 = Us[64 + k * 4 + 2], v3 = Us[64 + k * 4 + 3];
        #pragma unroll
        for (int p = 0; p < 4; p++) {
            float sr = u0.x * r[p][0]  + u0.y * r[p][1]  + u0.z * r[p][2]  + u0.w * r[p][3]
                     + u1.x * r[p][4]  + u1.y * r[p][5]  + u1.z * r[p][6]  + u1.w * r[p][7]
                     + u2.x * r[p][8]  + u2.y * r[p][9]  + u2.z * r[p][10] + u2.w * r[p][11]
                     + u3.x * r[p][12] + u3.y * r[p][13] + u3.z * r[p][14] + u3.w * r[p][15];
            float si = v0.x * r[p][0]  + v0.y * r[p][1]  + v0.z * r[p][2]  + v0.w * r[p][3]
                     + v1.x * r[p][4]  + v1.y * r[p][5]  + v1.z * r[p][6]  + v1.w * r[p][7]
                     + v2.x * r[p][8]  + v2.y * r[p][9]  + v2.z * r[p][10] + v2.w * r[p][11]
                     + v3.x * r[p][12] + v3.y * r[p][13] + v3.z * r[p][14] + v3.w * r[p][15];
            float pk = sr * sr + si * si;
            ez[p][0] += (k & 8) ? -pk : pk;
            ez[p][1] += (k & 4) ? -pk : pk;
            ez[p][2] += (k & 2) ? -pk : pk;
            ez[p][3] += (k & 1) ? -pk : pk;
        }
    }

    #pragma unroll
    for (int w = 0; w < 4; w++) {
        float m = fmaxf(fmaxf(ez[0][w], ez[1][w]), fmaxf(ez[2][w], ez[3][w]));
        g_h1[w * H1_PLANE + py * H1_STRIDE + px] = 1.f / (1.f + __expf(-m));
    }
}

// ---------------------------------------------------------------------------
// k_conv2: 5x5 conv (4->20) + relu + pool2 -> g_h2.
// Scalar 2co x 2pp (best measured). Block (16,8) covers 32x8 pooled px.
// Grid (4,16,10) = 640 blocks.
// ---------------------------------------------------------------------------
__global__ void __launch_bounds__(128) k_conv2(const float* __restrict__ w2,
                                               const float* __restrict__ b2) {
    int cog = blockIdx.z;                      // co = cog*2, cog*2+1
    __shared__ float ws[2][100];
    __shared__ __align__(16) float tile[4][20][68];
    int tx = threadIdx.x, ty = threadIdx.y;
    int tid = ty * 16 + tx;

    for (int q = tid; q < 200; q += 128) {
        int co = q / 100, rr = q % 100;
        ws[co][rr] = w2[(cog * 2 + co) * 100 + rr];
    }

    int ix0 = blockIdx.x * 64, iy0 = blockIdx.y * 16;   // pre-pool origin
    for (int q = tid; q < 4 * 20 * 17; q += 128) {
        int ci = q / 340, rem = q % 340, ry = rem / 17, f4 = rem % 17;
        int gy = iy0 + ry, gx = ix0 + f4 * 4;
        float4 v = make_float4(0.f, 0.f, 0.f, 0.f);
        if (gy < 255) {
            const float* src = &g_h1[ci * H1_PLANE + gy * H1_STRIDE + gx];
            if (gx + 3 < 255) {
                v = *(const float4*)src;
            } else {
                if (gx + 0 < 255) v.x = src[0];
                if (gx + 1 < 255) v.y = src[1];
                if (gx + 2 < 255) v.z = src[2];
                if (gx + 3 < 255) v.w = src[3];
            }
        }
        *(float4*)&tile[ci][ry][f4 * 4] = v;
    }
    __syncthreads();

    float acc[2][2][4];
    #pragma unroll
    for (int co = 0; co < 2; co++)
        #pragma unroll
        for (int pp = 0; pp < 2; pp++)
            #pragma unroll
            for (int q = 0; q < 4; q++) acc[co][pp][q] = 0.f;

    int ly = 2 * ty, lx = 4 * tx;              // local pre-pool origin
    #pragma unroll
    for (int ci = 0; ci < 4; ci++) {
        float patch[6][8];
        #pragma unroll
        for (int rr = 0; rr < 6; rr++) {
            const float4* rp = (const float4*)&tile[ci][ly + rr][lx];
            float4 v0 = rp[0], v1 = rp[1];
            patch[rr][0] = v0.x; patch[rr][1] = v0.y;
            patch[rr][2] = v0.z; patch[rr][3] = v0.w;
            patch[rr][4] = v1.x; patch[rr][5] = v1.y;
            patch[rr][6] = v1.z; patch[rr][7] = v1.w;
        }
        #pragma unroll
        for (int co = 0; co < 2; co++) {
            #pragma unroll
            for (int ky = 0; ky < 5; ky++) {
                #pragma unroll
                for (int kx = 0; kx < 5; kx++) {
                    float wv = ws[co][ci * 25 + ky * 5 + kx];
                    #pragma unroll
                    for (int pp = 0; pp < 2; pp++) {
                        int c = 2 * pp + kx;
                        acc[co][pp][0] += wv * patch[ky][c];
                        acc[co][pp][1] += wv * patch[ky][c + 1];
                        acc[co][pp][2] += wv * patch[ky + 1][c];
                        acc[co][pp][3] += wv * patch[ky + 1][c + 1];
                    }
                }
            }
        }
    }

    int py = blockIdx.y * 8 + ty;
    #pragma unroll
    for (int co = 0; co < 2; co++) {
        float bb = b2[cog * 2 + co];
        #pragma unroll
        for (int pp = 0; pp < 2; pp++) {
            int px = blockIdx.x * 32 + 2 * tx + pp;
            if (px >= 125 || py >= 125) continue;
            float m = fmaxf(fmaxf(acc[co][pp][0], acc[co][pp][1]),
                            fmaxf(acc[co][pp][2], acc[co][pp][3]));
            m = fmaxf(m + bb, 0.f);
            g_h2[(cog * 2 + co) * H2_PLANE + py * H2_STRIDE + px] = m;
        }
    }
}

// ---------------------------------------------------------------------------
// k_conv3: 3x3 conv (20->40) + relu + adaptive-max + (last block) FC stack.
// Block (16,16): two ty-halves = two co-pairs sharing one double-buffered
// tile. Thread: 2 horiz px; f32x2 lanes = co pair. Grid (4,16,10) = 640.
// Bins over 123: bin b = [floor(b*123/4), ceil((b+1)*123/4)); overlap rows
// 30,61,92 also belong to the NEXT bin.
// Last-block FC uses writer-only fences (threadFenceReduction pattern).
// ---------------------------------------------------------------------------
__global__ void __launch_bounds__(256) k_conv3(const float* __restrict__ w3,
                                               const float* __restrict__ b3,
                                               const float* __restrict__ fw1,
                                               const float* __restrict__ fb1,
                                               const float* __restrict__ fw2,
                                               const float* __restrict__ fb2,
                                               float* __restrict__ out) {
    int cog2 = blockIdx.z;                     // co base = cog2*4
    __shared__ u64 ws2[2][180];                // [half] (w_co0, w_co1)
    __shared__ __align__(16) float tile[2][5][10][36];
    __shared__ int sbins[4][16];
    int tx = threadIdx.x, ty = threadIdx.y;
    int tid = ty * 16 + tx;
    int half = ty >> 3;                        // 0/1 -> co pair
    int tyl  = ty & 7;                         // row within 8-row band

    for (int q = tid; q < 360; q += 256) {
        int h = q / 180, rr = q % 180;
        ws2[h][rr] = f2pack(w3[(cog2 * 4 + h * 2 + 0) * 180 + rr],
                            w3[(cog2 * 4 + h * 2 + 1) * 180 + rr]);
    }
    if (tid < 64) ((int*)sbins)[tid] = 0;

    int px0 = blockIdx.x * 32, py0 = blockIdx.y * 8;
    int lx = 2 * tx;

    auto fill = [&](int c, int b) {
        for (int q = tid; q < 450; q += 256) {
            int cil = q / 90, rem = q % 90, ry = rem / 9, f4 = rem % 9;
            int gy = py0 + ry, gx = px0 + f4 * 4;
            float4 v = make_float4(0.f, 0.f, 0.f, 0.f);
            if (gy < 125 && gx < 125) {
                const float* src = &g_h2[(c * 5 + cil) * H2_PLANE + gy * H2_STRIDE + gx];
                if (gx + 3 < 125) {
                    v = *(const float4*)src;
                } else {
                    v.x = src[0];
                    if (gx + 1 < 125) v.y = src[1];
                    if (gx + 2 < 125) v.z = src[2];
                }
            }
            *(float4*)&tile[b][cil][ry][f4 * 4] = v;
        }
    };

    fill(0, 0);
    __syncthreads();

    u64 acc2[2] = {0ull, 0ull};                // 2 px, lanes = co pair

    for (int c4 = 0; c4 < 4; c4++) {
        int buf = c4 & 1;
        if (c4 < 3) fill(c4 + 1, buf ^ 1);     // overlap next chunk's loads

        #pragma unroll
        for (int cil = 0; cil < 5; cil++) {
            int ci = c4 * 5 + cil;
            float f[3][4];
            #pragma unroll
            for (int rr = 0; rr < 3; rr++) {
                const float2* rp = (const float2*)&tile[buf][cil][tyl + rr][lx];
                float2 v0 = rp[0], v1 = rp[1];
                f[rr][0] = v0.x; f[rr][1] = v0.y;
                f[rr][2] = v1.x; f[rr][3] = v1.y;
            }
            u64 p2[3][4];
            #pragma unroll
            for (int rr = 0; rr < 3; rr++)
                #pragma unroll
                for (int c = 0; c < 4; c++) p2[rr][c] = f2pack(f[rr][c], f[rr][c]);

            #pragma unroll
            for (int ky = 0; ky < 3; ky++) {
                #pragma unroll
                for (int kx = 0; kx < 3; kx++) {
                    u64 wv = ws2[half][ci * 9 + ky * 3 + kx];
                    acc2[0] = f2fma(wv, p2[ky][kx], acc2[0]);
                    acc2[1] = f2fma(wv, p2[ky][kx + 1], acc2[1]);
                }
            }
        }
        __syncthreads();
    }

    int gy = py0 + tyl;
    if (gy < 123) {
        int bi = (gy * 4) / 123; if (bi > 3) bi = 3;
        bool oy = (bi < 3) && (gy >= (((bi + 1) * 123) >> 2));
        float bb0 = b3[cog2 * 4 + half * 2 + 0];
        float bb1 = b3[cog2 * 4 + half * 2 + 1];
        int r0 = half * 2, r1 = half * 2 + 1;
        #pragma unroll
        for (int dx = 0; dx < 2; dx++) {
            int gx = px0 + lx + dx;
            if (gx >= 123) continue;
            float a0, a1;
            f2unpack(acc2[dx], a0, a1);
            float v0 = fmaxf(a0 + bb0, 0.f);
            float v1 = fmaxf(a1 + bb1, 0.f);
            int iv0 = __float_as_int(v0), iv1 = __float_as_int(v1);
            int bj = (gx * 4) / 123; if (bj > 3) bj = 3;
            bool ox = (bj < 3) && (gx >= (((bj + 1) * 123) >> 2));
            atomicMax(&sbins[r0][bi * 4 + bj], iv0);
            atomicMax(&sbins[r1][bi * 4 + bj], iv1);
            if (oy) { atomicMax(&sbins[r0][(bi + 1) * 4 + bj], iv0);
                      atomicMax(&sbins[r1][(bi + 1) * 4 + bj], iv1); }
            if (ox) { atomicMax(&sbins[r0][bi * 4 + (bj + 1)], iv0);
                      atomicMax(&sbins[r1][bi * 4 + (bj + 1)], iv1); }
            if (oy && ox) { atomicMax(&sbins[r0][(bi + 1) * 4 + (bj + 1)], iv0);
                            atomicMax(&sbins[r1][(bi + 1) * 4 + (bj + 1)], iv1); }
        }
    }
    __syncthreads();
    if (tid < 64) {
        int co = tid >> 4, b = tid & 15;
        atomicMax((int*)&g_bins[(cog2 * 4 + co) * 16 + b], sbins[co][b]);
        __threadfence();                        // writers only (2 warps)
    }

    // ---- last-block FC: 640 -> 64 (relu) -> 10 ----
    __shared__ int s_last;
    __syncthreads();                            // writers' fences complete
    if (tid == 0) {
        int prev = atomicAdd(&g_done, 1);
        s_last = (prev == CONV3_BLOCKS - 1) ? 1 : 0;
    }
    __syncthreads();
    if (!s_last) return;

    if (tid == 0) g_done = 0;                   // reset for next graph replay

    __shared__ float h[640];
    __shared__ float f1[64];
    for (int i = tid; i < 640; i += 256) h[i] = __ldcg(&g_bins[i]);
    __syncthreads();

    int warp = tid >> 5, lane = tid & 31;
    #pragma unroll
    for (int k = 0; k < 8; k++) {
        int n = warp * 8 + k;
        float s = 0.f;
        for (int j = lane; j < 640; j += 32) s += fw1[n * 640 + j] * h[j];
        s += __shfl_xor_sync(0xffffffffu, s, 16);
        s += __shfl_xor_sync(0xffffffffu, s, 8);
        s += __shfl_xor_sync(0xffffffffu, s, 4);
        s += __shfl_xor_sync(0xffffffffu, s, 2);
        s += __shfl_xor_sync(0xffffffffu, s, 1);
        if (lane == 0) f1[n] = fmaxf(s + fb1[n], 0.f);
    }
    __syncthreads();
    if (tid < 10) {
        float a = fb2[tid];
        #pragma unroll
        for (int j = 0; j < 64; j++) a += fw2[tid * 64 + j] * f1[j];
        out[tid] = a;
    }
}

// ---------------------------------------------------------------------------
extern "C" void kernel_launch(void* const* d_in, const int* in_sizes, int n_in,
                              void* d_out, int out_size) {
    const float* x   = (const float*)d_in[0];
    const float* qw  = (const float*)d_in[1];
    const float* c2w = (const float*)d_in[2];
    const float* c2b = (const float*)d_in[3];
    const float* c3w = (const float*)d_in[4];
    const float* c3b = (const float*)d_in[5];
    const float* f1w = (const float*)d_in[6];
    const float* f1b = (const float*)d_in[7];
    const float* f2w = (const float*)d_in[8];
    const float* f2b = (const float*)d_in[9];

    k_prep<<<1, 256>>>(qw);

    dim3 bq(16, 8), gq(16, 32);
    k_qconv<<<gq, bq>>>(x);

    dim3 bc(16, 8);
    dim3 g2(4, 16, 10);
    k_conv2<<<g2, bc>>>(c2w, c2b);

    dim3 bc3(16, 16);
    dim3 g3(4, 16, 10);
    k_conv3<<<g3, bc3>>>(c3w, c3b, f1w, f1b, f2w, f2b, (float*)d_out);
}

// round 14
// speedup vs baseline: 1.0905x; 1.0381x over previous
#include <cuda_runtime.h>
#include <math.h>

// ---------------------------------------------------------------------------
// SimpleNet quanvolutional pipeline, sm_103a
//   g_h1: [4][255][256]  (row stride 256)
//   g_h2: [20][125][128] (row stride 128)
// R10 best-measured kernels; FC parallelized: 64 blocks (one fc1 neuron each),
// fc2 in the last-finished block.
// ---------------------------------------------------------------------------

typedef unsigned long long u64;

__device__ __forceinline__ u64 f2pack(float lo, float hi) {
    u64 r; asm("mov.b64 %0, {%1, %2};" : "=l"(r) : "f"(lo), "f"(hi)); return r;
}
__device__ __forceinline__ void f2unpack(u64 v, float& lo, float& hi) {
    asm("mov.b64 {%0, %1}, %2;" : "=f"(lo), "=f"(hi) : "l"(v));
}
__device__ __forceinline__ u64 f2fma(u64 a, u64 b, u64 c) {
    u64 d; asm("fma.rn.f32x2 %0, %1, %2, %3;" : "=l"(d) : "l"(a), "l"(b), "l"(c)); return d;
}

__device__ float g_U[512];                 // [2][16][16]: Wr rows then Wi rows
__device__ float g_h1[4 * 255 * 256];
__device__ float g_h2[20 * 125 * 128];
__device__ float g_bins[640];              // adaptive-max bins (atomicMax as int)
__device__ float g_f1[64];                 // fc1 activations
__device__ int   g_done;                   // fc1 completion counter (self-resetting)

#define H1_STRIDE 256
#define H1_PLANE  (255 * 256)
#define H2_STRIDE 128
#define H2_PLANE  (125 * 128)

// ---------------------------------------------------------------------------
// k_prep: simulate weight circuit -> U, export W[k][j] = U[k][j]*(-i)^popc(j).
// Zero adaptive-max bins.
// ---------------------------------------------------------------------------
__global__ void k_prep(const float* __restrict__ qw) {
    int t = threadIdx.x;                 // 0..255
    for (int b = t; b < 640; b += 256) ((int*)g_bins)[b] = 0;

    __shared__ float Ur[16][16], Ui[16][16];

    if (t < 16) {
        int k = t;
        float pr[16], pi[16];
        #pragma unroll
        for (int i = 0; i < 16; i++) { pr[i] = (i == k) ? 1.f : 0.f; pi[i] = 0.f; }

        for (int l = 0; l < 3; l++) {
            for (int w = 0; w < 4; w++) {
                float phi = qw[(l * 4 + w) * 3 + 0];
                float th  = qw[(l * 4 + w) * 3 + 1];
                float om  = qw[(l * 4 + w) * 3 + 2];
                float st, ct, sap, cap, sam, cam;
                sincosf(0.5f * th, &st, &ct);
                sincosf(0.5f * (phi + om), &sap, &cap);
                sincosf(0.5f * (phi - om), &sam, &cam);
                float u00r =  cap * ct, u00i = -sap * ct;
                float u01r = -cam * st, u01i = -sam * st;
                float u10r =  cam * st, u10i = -sam * st;
                float u11r =  cap * ct, u11i =  sap * ct;
                int m = 8 >> w;
                for (int i0 = 0; i0 < 16; i0++) {
                    if (i0 & m) continue;
                    int i1 = i0 | m;
                    float a0r = pr[i0], a0i = pi[i0];
                    float a1r = pr[i1], a1i = pi[i1];
                    pr[i0] = u00r * a0r - u00i * a0i + u01r * a1r - u01i * a1i;
                    pi[i0] = u00r * a0i + u00i * a0r + u01r * a1i + u01i * a1r;
                    pr[i1] = u10r * a0r - u10i * a0i + u11r * a1r - u11i * a1i;
                    pi[i1] = u10r * a0i + u10i * a0r + u11r * a1i + u11i * a1r;
                }
            }
            int r = l % 3 + 1;
            for (int w = 0; w < 4; w++) {
                int cm = 8 >> w;
                int tm = 8 >> ((w + r) & 3);
                for (int i = 0; i < 16; i++) {
                    if ((i & cm) && !(i & tm)) {
                        int j = i | tm;
                        float tr = pr[i], ti = pi[i];
                        pr[i] = pr[j]; pi[i] = pi[j];
                        pr[j] = tr;    pi[j] = ti;
                    }
                }
            }
        }
        #pragma unroll
        for (int i = 0; i < 16; i++) { Ur[i][k] = pr[i]; Ui[i][k] = pi[i]; }
    }
    __syncthreads();

    int i = t >> 4, j = t & 15;
    float ur = Ur[i][j], ui = Ui[i][j];
    int d = __popc(j) & 3;
    float wr = (d == 0) ? ur : (d == 1) ? ui : (d == 2) ? -ur : -ui;
    float wi = (d == 0) ? ui : (d == 1) ? -ur : (d == 2) ? -ui : ur;
    g_U[t]       = wr;
    g_U[256 + t] = wi;
}

// ---------------------------------------------------------------------------
// k_qconv: scalar form (best measured). psi = W r per patch; ez; max-pool;
// sigmoid -> g_h1.
// ---------------------------------------------------------------------------
__global__ void __launch_bounds__(128) k_qconv(const float* __restrict__ img) {
    __shared__ __align__(16) float4 Us[128];   // Wr rows (64 f4) then Wi rows
    {
        int tid = threadIdx.y * 16 + threadIdx.x;
        if (tid < 128) Us[tid] = ((const float4*)g_U)[tid];
    }
    __syncthreads();

    int px = blockIdx.x * 16 + threadIdx.x;
    int py = blockIdx.y * 8 + threadIdx.y;
    if (px >= 255 || py >= 255) return;

    float cc[9], ss[9];
    int y0 = 2 * py, x0 = 2 * px;
    #pragma unroll
    for (int d = 0; d < 9; d++) {
        int dy = d / 3, dx = d % 3;
        float v = 0.5f * img[(y0 + dy) * 512 + (x0 + dx)];
        __sincosf(v, &ss[d], &cc[d]);
    }

    float r[4][16];
    #pragma unroll
    for (int p = 0; p < 4; p++) {
        int dy = p >> 1, dx = p & 1;
        int ia = dy * 3 + dx, ib = ia + 1, ic = ia + 3, id = ia + 4;
        float c0 = cc[ia], s0 = ss[ia], c1 = cc[ib], s1 = ss[ib];
        float c2 = cc[ic], s2 = ss[ic], c3 = cc[id], s3 = ss[id];
        float hi[4] = { c0 * c1, c0 * s1, s0 * c1, s0 * s1 };
        float lo[4] = { c2 * c3, c2 * s3, s2 * c3, s2 * s3 };
        #pragma unroll
        for (int a = 0; a < 4; a++)
            #pragma unroll
            for (int b = 0; b < 4; b++)
                r[p][a * 4 + b] = hi[a] * lo[b];
    }

    float ez[4][4];
    #pragma unroll
    for (int p = 0; p < 4; p++)
        #pragma unroll
        for (int w = 0; w < 4; w++) ez[p][w] = 0.f;

    #pragma unroll
    for (int k = 0; k < 16; k++) {
        float4 u0 = Us[k * 4 + 0], u1 = Us[k * 4 + 1];
        float4 u2 = Us[k * 4 + 2], u3 = Us[k * 4 + 3];
        float4 v0 = Us[64 + k * 4 + 0], v1 = Us[64 + k * 4 + 1];
        float4 v2 = Us[64 + k * 4 + 2], v3 = Us[64 + k * 4 + 3];
        #pragma unroll
        for (int p = 0; p < 4; p++) {
            float sr = u0.x * r[p][0]  + u0.y * r[p][1]  + u0.z * r[p][2]  + u0.w * r[p][3]
                     + u1.x * r[p][4]  + u1.y * r[p][5]  + u1.z * r[p][6]  + u1.w * r[p][7]
                     + u2.x * r[p][8]  + u2.y * r[p][9]  + u2.z * r[p][10] + u2.w * r[p][11]
                     + u3.x * r[p][12] + u3.y * r[p][13] + u3.z * r[p][14] + u3.w * r[p][15];
            float si = v0.x * r[p][0]  + v0.y * r[p][1]  + v0.z * r[p][2]  + v0.w * r[p][3]
                     + v1.x * r[p][4]  + v1.y * r[p][5]  + v1.z * r[p][6]  + v1.w * r[p][7]
                     + v2.x * r[p][8]  + v2.y * r[p][9]  + v2.z * r[p][10] + v2.w * r[p][11]
                     + v3.x * r[p][12] + v3.y * r[p][13] + v3.z * r[p][14] + v3.w * r[p][15];
            float pk = sr * sr + si * si;
            ez[p][0] += (k & 8) ? -pk : pk;
            ez[p][1] += (k & 4) ? -pk : pk;
            ez[p][2] += (k & 2) ? -pk : pk;
            ez[p][3] += (k & 1) ? -pk : pk;
        }
    }

    #pragma unroll
    for (int w = 0; w < 4; w++) {
        float m = fmaxf(fmaxf(ez[0][w], ez[1][w]), fmaxf(ez[2][w], ez[3][w]));
        g_h1[w * H1_PLANE + py * H1_STRIDE + px] = 1.f / (1.f + __expf(-m));
    }
}

// ---------------------------------------------------------------------------
// k_conv2: 5x5 conv (4->20) + relu + pool2 -> g_h2.
// Scalar 2co x 2pp (best measured). Block (16,8) covers 32x8 pooled px.
// Grid (4,16,10) = 640 blocks.
// ---------------------------------------------------------------------------
__global__ void __launch_bounds__(128) k_conv2(const float* __restrict__ w2,
                                               const float* __restrict__ b2) {
    int cog = blockIdx.z;                      // co = cog*2, cog*2+1
    __shared__ float ws[2][100];
    __shared__ __align__(16) float tile[4][20][68];
    int tx = threadIdx.x, ty = threadIdx.y;
    int tid = ty * 16 + tx;

    for (int q = tid; q < 200; q += 128) {
        int co = q / 100, rr = q % 100;
        ws[co][rr] = w2[(cog * 2 + co) * 100 + rr];
    }

    int ix0 = blockIdx.x * 64, iy0 = blockIdx.y * 16;   // pre-pool origin
    for (int q = tid; q < 4 * 20 * 17; q += 128) {
        int ci = q / 340, rem = q % 340, ry = rem / 17, f4 = rem % 17;
        int gy = iy0 + ry, gx = ix0 + f4 * 4;
        float4 v = make_float4(0.f, 0.f, 0.f, 0.f);
        if (gy < 255) {
            const float* src = &g_h1[ci * H1_PLANE + gy * H1_STRIDE + gx];
            if (gx + 3 < 255) {
                v = *(const float4*)src;
            } else {
                if (gx + 0 < 255) v.x = src[0];
                if (gx + 1 < 255) v.y = src[1];
                if (gx + 2 < 255) v.z = src[2];
                if (gx + 3 < 255) v.w = src[3];
            }
        }
        *(float4*)&tile[ci][ry][f4 * 4] = v;
    }
    __syncthreads();

    float acc[2][2][4];
    #pragma unroll
    for (int co = 0; co < 2; co++)
        #pragma unroll
        for (int pp = 0; pp < 2; pp++)
            #pragma unroll
            for (int q = 0; q < 4; q++) acc[co][pp][q] = 0.f;

    int ly = 2 * ty, lx = 4 * tx;              // local pre-pool origin
    #pragma unroll
    for (int ci = 0; ci < 4; ci++) {
        float patch[6][8];
        #pragma unroll
        for (int rr = 0; rr < 6; rr++) {
            const float4* rp = (const float4*)&tile[ci][ly + rr][lx];
            float4 v0 = rp[0], v1 = rp[1];
            patch[rr][0] = v0.x; patch[rr][1] = v0.y;
            patch[rr][2] = v0.z; patch[rr][3] = v0.w;
            patch[rr][4] = v1.x; patch[rr][5] = v1.y;
            patch[rr][6] = v1.z; patch[rr][7] = v1.w;
        }
        #pragma unroll
        for (int co = 0; co < 2; co++) {
            #pragma unroll
            for (int ky = 0; ky < 5; ky++) {
                #pragma unroll
                for (int kx = 0; kx < 5; kx++) {
                    float wv = ws[co][ci * 25 + ky * 5 + kx];
                    #pragma unroll
                    for (int pp = 0; pp < 2; pp++) {
                        int c = 2 * pp + kx;
                        acc[co][pp][0] += wv * patch[ky][c];
                        acc[co][pp][1] += wv * patch[ky][c + 1];
                        acc[co][pp][2] += wv * patch[ky + 1][c];
                        acc[co][pp][3] += wv * patch[ky + 1][c + 1];
                    }
                }
            }
        }
    }

    int py = blockIdx.y * 8 + ty;
    #pragma unroll
    for (int co = 0; co < 2; co++) {
        float bb = b2[cog * 2 + co];
        #pragma unroll
        for (int pp = 0; pp < 2; pp++) {
            int px = blockIdx.x * 32 + 2 * tx + pp;
            if (px >= 125 || py >= 125) continue;
            float m = fmaxf(fmaxf(acc[co][pp][0], acc[co][pp][1]),
                            fmaxf(acc[co][pp][2], acc[co][pp][3]));
            m = fmaxf(m + bb, 0.f);
            g_h2[(cog * 2 + co) * H2_PLANE + py * H2_STRIDE + px] = m;
        }
    }
}

// ---------------------------------------------------------------------------
// k_conv3: 3x3 conv (20->40) + relu + adaptive-max.  (pure R10 best.)
// Block (16,16): two ty-halves = two co-pairs sharing one double-buffered
// tile. Thread: 2 horiz px; f32x2 lanes = co pair. Grid (4,16,10).
// Bins over 123: bin b = [floor(b*123/4), ceil((b+1)*123/4)); overlap rows
// 30,61,92 also belong to the NEXT bin.
// ---------------------------------------------------------------------------
__global__ void __launch_bounds__(256) k_conv3(const float* __restrict__ w3,
                                               const float* __restrict__ b3) {
    int cog2 = blockIdx.z;                     // co base = cog2*4
    __shared__ u64 ws2[2][180];                // [half] (w_co0, w_co1)
    __shared__ __align__(16) float tile[2][5][10][36];
    __shared__ int sbins[4][16];
    int tx = threadIdx.x, ty = threadIdx.y;
    int tid = ty * 16 + tx;
    int half = ty >> 3;                        // 0/1 -> co pair
    int tyl  = ty & 7;                         // row within 8-row band

    for (int q = tid; q < 360; q += 256) {
        int h = q / 180, rr = q % 180;
        ws2[h][rr] = f2pack(w3[(cog2 * 4 + h * 2 + 0) * 180 + rr],
                            w3[(cog2 * 4 + h * 2 + 1) * 180 + rr]);
    }
    if (tid < 64) ((int*)sbins)[tid] = 0;

    int px0 = blockIdx.x * 32, py0 = blockIdx.y * 8;
    int lx = 2 * tx;

    auto fill = [&](int c, int b) {
        for (int q = tid; q < 450; q += 256) {
            int cil = q / 90, rem = q % 90, ry = rem / 9, f4 = rem % 9;
            int gy = py0 + ry, gx = px0 + f4 * 4;
            float4 v = make_float4(0.f, 0.f, 0.f, 0.f);
            if (gy < 125 && gx < 125) {
                const float* src = &g_h2[(c * 5 + cil) * H2_PLANE + gy * H2_STRIDE + gx];
                if (gx + 3 < 125) {
                    v = *(const float4*)src;
                } else {
                    v.x = src[0];
                    if (gx + 1 < 125) v.y = src[1];
                    if (gx + 2 < 125) v.z = src[2];
                }
            }
            *(float4*)&tile[b][cil][ry][f4 * 4] = v;
        }
    };

    fill(0, 0);
    __syncthreads();

    u64 acc2[2] = {0ull, 0ull};                // 2 px, lanes = co pair

    for (int c4 = 0; c4 < 4; c4++) {
        int buf = c4 & 1;
        if (c4 < 3) fill(c4 + 1, buf ^ 1);     // overlap next chunk's loads

        #pragma unroll
        for (int cil = 0; cil < 5; cil++) {
            int ci = c4 * 5 + cil;
            float f[3][4];
            #pragma unroll
            for (int rr = 0; rr < 3; rr++) {
                const float2* rp = (const float2*)&tile[buf][cil][tyl + rr][lx];
                float2 v0 = rp[0], v1 = rp[1];
                f[rr][0] = v0.x; f[rr][1] = v0.y;
                f[rr][2] = v1.x; f[rr][3] = v1.y;
            }
            u64 p2[3][4];
            #pragma unroll
            for (int rr = 0; rr < 3; rr++)
                #pragma unroll
                for (int c = 0; c < 4; c++) p2[rr][c] = f2pack(f[rr][c], f[rr][c]);

            #pragma unroll
            for (int ky = 0; ky < 3; ky++) {
                #pragma unroll
                for (int kx = 0; kx < 3; kx++) {
                    u64 wv = ws2[half][ci * 9 + ky * 3 + kx];
                    acc2[0] = f2fma(wv, p2[ky][kx], acc2[0]);
                    acc2[1] = f2fma(wv, p2[ky][kx + 1], acc2[1]);
                }
            }
        }
        __syncthreads();
    }

    int gy = py0 + tyl;
    if (gy < 123) {
        int bi = (gy * 4) / 123; if (bi > 3) bi = 3;
        bool oy = (bi < 3) && (gy >= (((bi + 1) * 123) >> 2));
        float bb0 = b3[cog2 * 4 + half * 2 + 0];
        float bb1 = b3[cog2 * 4 + half * 2 + 1];
        int r0 = half * 2, r1 = half * 2 + 1;
        #pragma unroll
        for (int dx = 0; dx < 2; dx++) {
            int gx = px0 + lx + dx;
            if (gx >= 123) continue;
            float a0, a1;
            f2unpack(acc2[dx], a0, a1);
            float v0 = fmaxf(a0 + bb0, 0.f);
            float v1 = fmaxf(a1 + bb1, 0.f);
            int iv0 = __float_as_int(v0), iv1 = __float_as_int(v1);
            int bj = (gx * 4) / 123; if (bj > 3) bj = 3;
            bool ox = (bj < 3) && (gx >= (((bj + 1) * 123) >> 2));
            atomicMax(&sbins[r0][bi * 4 + bj], iv0);
            atomicMax(&sbins[r1][bi * 4 + bj], iv1);
            if (oy) { atomicMax(&sbins[r0][(bi + 1) * 4 + bj], iv0);
                      atomicMax(&sbins[r1][(bi + 1) * 4 + bj], iv1); }
            if (ox) { atomicMax(&sbins[r0][bi * 4 + (bj + 1)], iv0);
                      atomicMax(&sbins[r1][bi * 4 + (bj + 1)], iv1); }
            if (oy && ox) { atomicMax(&sbins[r0][(bi + 1) * 4 + (bj + 1)], iv0);
                            atomicMax(&sbins[r1][(bi + 1) * 4 + (bj + 1)], iv1); }
        }
    }
    __syncthreads();
    if (tid < 64) {
        int co = tid >> 4, b = tid & 15;
        atomicMax((int*)&g_bins[(cog2 * 4 + co) * 16 + b], sbins[co][b]);
    }
}

// ---------------------------------------------------------------------------
// k_fc_wide: grid = 64 blocks x 128 threads. Block n computes fc1 neuron n
// (dot of 640). The last-finished block computes fc2 (10x64) -> out.
// ---------------------------------------------------------------------------
__global__ void __launch_bounds__(128) k_fc_wide(const float* __restrict__ w1,
                                                 const float* __restrict__ b1,
                                                 const float* __restrict__ w2,
                                                 const float* __restrict__ b2,
                                                 float* __restrict__ out) {
    int n = blockIdx.x;                        // fc1 neuron
    int t = threadIdx.x;
    __shared__ float red[4];
    __shared__ int s_last;

    float s = 0.f;
    const float* wrow = &w1[n * 640];
    for (int j = t; j < 640; j += 128) s += wrow[j] * g_bins[j];
    s += __shfl_xor_sync(0xffffffffu, s, 16);
    s += __shfl_xor_sync(0xffffffffu, s, 8);
    s += __shfl_xor_sync(0xffffffffu, s, 4);
    s += __shfl_xor_sync(0xffffffffu, s, 2);
    s += __shfl_xor_sync(0xffffffffu, s, 1);
    if ((t & 31) == 0) red[t >> 5] = s;
    __syncthreads();

    if (t == 0) {
        float v = red[0] + red[1] + red[2] + red[3];
        g_f1[n] = fmaxf(v + b1[n], 0.f);
        __threadfence();
        int prev = atomicAdd(&g_done, 1);
        s_last = (prev == 63) ? 1 : 0;
    }
    __syncthreads();
    if (!s_last) return;

    if (t == 0) g_done = 0;                    // reset for next graph replay

    __shared__ float f1[64];
    if (t < 64) f1[t] = __ldcg(&g_f1[t]);
    __syncthreads();

    if (t < 10) {
        float a = b2[t];
        #pragma unroll
        for (int j = 0; j < 64; j++) a += w2[t * 64 + j] * f1[j];
        out[t] = a;
    }
}

// ---------------------------------------------------------------------------
extern "C" void kernel_launch(void* const* d_in, const int* in_sizes, int n_in,
                              void* d_out, int out_size) {
    const float* x   = (const float*)d_in[0];
    const float* qw  = (const float*)d_in[1];
    const float* c2w = (const float*)d_in[2];
    const float* c2b = (const float*)d_in[3];
    const float* c3w = (const float*)d_in[4];
    const float* c3b = (const float*)d_in[5];
    const float* f1w = (const float*)d_in[6];
    const float* f1b = (const float*)d_in[7];
    const float* f2w = (const float*)d_in[8];
    const float* f2b = (const float*)d_in[9];

    k_prep<<<1, 256>>>(qw);

    dim3 bq(16, 8), gq(16, 32);
    k_qconv<<<gq, bq>>>(x);

    dim3 bc(16, 8);
    dim3 g2(4, 16, 10);
    k_conv2<<<g2, bc>>>(c2w, c2b);

    dim3 bc3(16, 16);
    dim3 g3(4, 16, 10);
    k_conv3<<<g3, bc3>>>(c3w, c3b);

    k_fc_wide<<<64, 128>>>(f1w, f1b, f2w, f2b, (float*)d_out);
}